// round 14
// baseline (speedup 1.0000x reference)
#include <cuda_runtime.h>
#include <cuda_fp16.h>

#define NN 100000
#define NE 1600000
#define C_IN 64
#define C_HID 128
#define NG 64
#define NC 10
#define NBLK ((NN + 255) / 256)    // 391
#define NTILE1 ((NN + 63) / 64)    // 1563
#define NTILE2 ((NN + 127) / 128)  // 782

// ---------------- scratch (__device__ globals; no allocations) ----------------
static __device__ __align__(16) int    g_degi[NN];
static __device__ __align__(16) int    g_off[NN];
static __device__ __align__(16) float  g_dinv[NN];
static __device__ __align__(16) int    g_bsum[NBLK];
static __device__ __align__(16) int2   g_sd[NE];       // {src, dst | rank<<17}
static __device__ __align__(16) int2   g_edge[NE];     // CSR payload: {src, norm-bits}
static __device__ __align__(16) __half g_xh[(size_t)NN * C_IN];    // 12.8 MB
static __device__ __align__(16) __half g_h1h[(size_t)NN * C_HID];  // 25.6 MB
static __device__ __align__(16) __half g_w1h[C_IN * C_HID];
static __device__ __align__(16) __half g_w2h[C_HID * C_HID];
static __device__ __align__(16) float  g_pooled[NG * C_HID];
static __device__ __align__(16) float  g_cnt[NG];
static __device__ int g_is64;

__device__ __forceinline__ int read_idx(const void* p, long long i) {
    if (g_is64) return (int)((const long long*)p)[i];
    return ((const int*)p)[i];
}
__device__ __forceinline__ float2 h2f(unsigned u) {
    __half2 h = *(__half2*)&u;
    return __half22float2(h);
}
__device__ __forceinline__ unsigned s2u(const void* p) {
    return (unsigned)__cvta_generic_to_shared(p);
}

// ---------------- mma / ldmatrix helpers ----------------
__device__ __forceinline__ void mma_f16(float c[4], unsigned a0, unsigned a1,
                                        unsigned a2, unsigned a3,
                                        unsigned b0, unsigned b1) {
    asm volatile(
        "mma.sync.aligned.m16n8k16.row.col.f32.f16.f16.f32 "
        "{%0,%1,%2,%3}, {%4,%5,%6,%7}, {%8,%9}, {%0,%1,%2,%3};"
        : "+f"(c[0]), "+f"(c[1]), "+f"(c[2]), "+f"(c[3])
        : "r"(a0), "r"(a1), "r"(a2), "r"(a3), "r"(b0), "r"(b1));
}
__device__ __forceinline__ void ldsm_x4(unsigned& r0, unsigned& r1, unsigned& r2,
                                        unsigned& r3, unsigned addr) {
    asm volatile("ldmatrix.sync.aligned.m8n8.x4.shared.b16 {%0,%1,%2,%3}, [%4];"
                 : "=r"(r0), "=r"(r1), "=r"(r2), "=r"(r3) : "r"(addr));
}
__device__ __forceinline__ void ldsm_x4_t(unsigned& r0, unsigned& r1, unsigned& r2,
                                          unsigned& r3, unsigned addr) {
    asm volatile("ldmatrix.sync.aligned.m8n8.x4.trans.shared.b16 {%0,%1,%2,%3}, [%4];"
                 : "=r"(r0), "=r"(r1), "=r"(r2), "=r"(r3) : "r"(addr));
}

// GEMM phase: acc[8][4] += As[mt*16..+16, 0..K) x W[0..K, nh*64..+64)
template<int K, int LDA>
__device__ __forceinline__ void mma_gemm_phase(unsigned asb, unsigned wb, int lane,
                                               int mt, int nh, float acc[8][4]) {
    const int m0 = mt * 16;
    unsigned a_base = asb + (((m0 + (lane & 15)) * LDA) + ((lane >> 4) << 3)) * 2;
    const int brow = (lane & 7) + (lane & 8);
    const int bcol = nh * 64 + ((lane & 16) >> 1);
#pragma unroll
    for (int k0 = 0; k0 < K; k0 += 16) {
        unsigned a0, a1, a2, a3;
        ldsm_x4(a0, a1, a2, a3, a_base + k0 * 2);
#pragma unroll
        for (int p = 0; p < 4; ++p) {
            unsigned b0, b1, b2, b3;
            unsigned baddr = wb + (((k0 + brow) * 136) + bcol + p * 16) * 2;
            ldsm_x4_t(b0, b1, b2, b3, baddr);
            mma_f16(acc[2 * p],     a0, a1, a2, a3, b0, b1);
            mma_f16(acc[2 * p + 1], a0, a1, a2, a3, b2, b3);
        }
    }
}

// ---------------- init (zero) + dtype detect (block 0 thread 0) ----------------
__global__ __launch_bounds__(256) void k_init(const void* __restrict__ ei) {
    int t = blockIdx.x * 256 + threadIdx.x;
    if (t == 0) {
        const long long* p = (const long long*)ei;
        int ok64 = 1;
        for (int i = 0; i < 64; ++i) {
            long long v = p[i];
            if (v < 0 || v >= NN) { ok64 = 0; break; }
        }
        g_is64 = ok64;
    }
    if (t < NN) g_degi[t] = 0;
    if (t < NG * C_HID) g_pooled[t] = 0.0f;
    if (t < NG) g_cnt[t] = 0.0f;
}

// ---------------- fp16 conversions: x, W1, W2 in one kernel ----------------
#define NT_X  (NN * C_IN / 4)          // float4 items: 1,600,000
#define NT_W1 (C_IN * C_HID / 2)       // half2 items:  4096
#define NT_W2 (C_HID * C_HID / 2)      // half2 items:  8192
__global__ __launch_bounds__(256)
void k_convert(const float* __restrict__ X, const float* __restrict__ W1,
               const float* __restrict__ W2) {
    int i = blockIdx.x * 256 + threadIdx.x;
    if (i < NT_X) {
        float4 v = ((const float4*)X)[i];
        __half2 a = __floats2half2_rn(v.x, v.y);
        __half2 b = __floats2half2_rn(v.z, v.w);
        uint2 u;
        u.x = *(unsigned*)&a;
        u.y = *(unsigned*)&b;
        ((uint2*)g_xh)[i] = u;
    } else if (i < NT_X + NT_W1) {
        int j = i - NT_X;
        float2 v = ((const float2*)W1)[j];
        ((__half2*)g_w1h)[j] = __floats2half2_rn(v.x, v.y);
    } else if (i < NT_X + NT_W1 + NT_W2) {
        int j = i - NT_X - NT_W1;
        float2 v = ((const float2*)W2)[j];
        ((__half2*)g_w2h)[j] = __floats2half2_rn(v.x, v.y);
    }
}

// ---------------- edge prep: decode once, count degrees, capture rank ----------------
__global__ void k_edge_prep(const void* __restrict__ ei) {
    int e = blockIdx.x * blockDim.x + threadIdx.x;
    if (e >= NE) return;
    int s = read_idx(ei, e);
    int d = read_idx(ei, (long long)NE + e);
    s = min(max(s, 0), NN - 1);
    d = min(max(d, 0), NN - 1);
    int rank = atomicAdd(&g_degi[d], 1);       // within-row rank for free
    if (rank > 32767) rank = 32767;            // defensive (never hit for this data)
    g_sd[e] = make_int2(s, d | (rank << 17));  // dst < 2^17
}

// ---- block sums for scan + batch histogram (g_cnt zeroed in EARLIER kernel) ----
__global__ __launch_bounds__(256) void k_blocksum(const void* __restrict__ batch) {
    __shared__ int ws[8];
    __shared__ int h[NG];
    if (threadIdx.x < NG) h[threadIdx.x] = 0;
    int i = blockIdx.x * 256 + threadIdx.x;
    int v = (i < NN) ? g_degi[i] : 0;
    int lane = threadIdx.x & 31, wid = threadIdx.x >> 5;
#pragma unroll
    for (int o = 16; o > 0; o >>= 1) v += __shfl_down_sync(0xFFFFFFFFu, v, o);
    if (lane == 0) ws[wid] = v;
    __syncthreads();
    if (threadIdx.x == 0) {
        int s = 0;
#pragma unroll
        for (int w = 0; w < 8; ++w) s += ws[w];
        g_bsum[blockIdx.x] = s;
    }
    if (i < NN) {
        int g = read_idx(batch, i);
        g = min(max(g, 0), NG - 1);
        atomicAdd(&h[g], 1);
    }
    __syncthreads();
    if (threadIdx.x < NG && h[threadIdx.x] > 0)
        atomicAdd(&g_cnt[threadIdx.x], (float)h[threadIdx.x]);
}

// ---- offsets: inline exclusive block-prefix (sum g_bsum[0..bid)) + in-block scan ----
__global__ __launch_bounds__(256) void k_offsets() {
    __shared__ int ws2[8];
    __shared__ int ws[8];
    __shared__ int s_boff;
    int lane = threadIdx.x & 31, wid = threadIdx.x >> 5;

    // block offset = sum of g_bsum[0..blockIdx.x)
    int partial = 0;
    for (int i = threadIdx.x; i < blockIdx.x; i += 256) partial += g_bsum[i];
#pragma unroll
    for (int o = 16; o > 0; o >>= 1) partial += __shfl_down_sync(0xFFFFFFFFu, partial, o);
    if (lane == 0) ws2[wid] = partial;
    __syncthreads();
    if (threadIdx.x == 0) {
        int s = 0;
#pragma unroll
        for (int w = 0; w < 8; ++w) s += ws2[w];
        s_boff = s;
    }

    int i = blockIdx.x * 256 + threadIdx.x;
    int deg = (i < NN) ? g_degi[i] : 0;
    int v = deg;
#pragma unroll
    for (int o = 1; o < 32; o <<= 1) {
        int t = __shfl_up_sync(0xFFFFFFFFu, v, o);
        if (lane >= o) v += t;
    }
    if (lane == 31) ws[wid] = v;
    __syncthreads();
    if (wid == 0 && lane < 8) {
        int w = ws[lane];
#pragma unroll
        for (int o = 1; o < 8; o <<= 1) {
            int t = __shfl_up_sync(0xFFu, w, o);
            if (lane >= o) w += t;
        }
        ws[lane] = w;
    }
    __syncthreads();
    int excl = v - deg + (wid > 0 ? ws[wid - 1] : 0) + s_boff;
    if (i < NN) {
        g_off[i] = excl;
        g_dinv[i] = rsqrtf((float)(deg + 1));
    }
}

// fill CSR payload from decoded pairs — no atomics (rank precomputed)
__global__ void k_csr_fill() {
    int e = blockIdx.x * blockDim.x + threadIdx.x;
    if (e >= NE) return;
    int2 sd = g_sd[e];
    int d = sd.y & 0x1FFFF;
    int rank = ((unsigned)sd.y) >> 17;
    int pos = g_off[d] + rank;
    float nrm = g_dinv[sd.x] * g_dinv[d];
    g_edge[pos] = make_int2(sd.x, __float_as_int(nrm));
}

// ---------------- fused layer 1: gather-agg(x_h,64) + HMMA GEMM W1 + relu -> H1(fp16) ----------------
#define LDA1 72    // halves (row = 144B)
__global__ __launch_bounds__(256)
void k_fused1(const float* __restrict__ bias) {
    __shared__ __half As[64 * LDA1];     // 9.2 KB
    __shared__ __half Wh[64 * 136];      // 17.4 KB

    const int tid = threadIdx.x;
    const int lane = tid & 31;
    const int w = tid >> 5;
    const int node_base = blockIdx.x * 64;
    const unsigned* __restrict__ Xu = (const unsigned*)g_xh;
    const int2* __restrict__ E = g_edge;
    unsigned* As_u = (unsigned*)As;

    // load W1 fp16 into padded smem [64][136]
#pragma unroll
    for (int it = 0; it < 4; ++it) {
        int idx = tid + it * 256;              // uint4 chunks: 1024 total
        int row = idx >> 4, ch = idx & 15;
        uint4 v = ((const uint4*)g_w1h)[idx];
        *(uint4*)&Wh[row * 136 + ch * 8] = v;
    }

    // phase 1: warp-per-node gather aggregation, unroll 4
    for (int j = w; j < 64; j += 8) {
        int node = node_base + j;
        float2 acc;
        if (node < NN) {
            float di = g_dinv[node];
            float sw = di * di;
            acc = h2f(Xu[node * 32 + lane]);
            acc.x *= sw; acc.y *= sw;
            int beg = g_off[node];
            int cnt = g_degi[node];
            int k = 0;
            for (; k + 4 <= cnt; k += 4) {
                int2 e0 = E[beg + k];
                int2 e1 = E[beg + k + 1];
                int2 e2 = E[beg + k + 2];
                int2 e3 = E[beg + k + 3];
                float2 v0 = h2f(Xu[e0.x * 32 + lane]);
                float2 v1 = h2f(Xu[e1.x * 32 + lane]);
                float2 v2 = h2f(Xu[e2.x * 32 + lane]);
                float2 v3 = h2f(Xu[e3.x * 32 + lane]);
                float w0 = __int_as_float(e0.y);
                float w1 = __int_as_float(e1.y);
                float w2 = __int_as_float(e2.y);
                float w3 = __int_as_float(e3.y);
                acc.x += w0 * v0.x + w1 * v1.x + w2 * v2.x + w3 * v3.x;
                acc.y += w0 * v0.y + w1 * v1.y + w2 * v2.y + w3 * v3.y;
            }
            for (; k < cnt; ++k) {
                int2 e0 = E[beg + k];
                float w0 = __int_as_float(e0.y);
                float2 v0 = h2f(Xu[e0.x * 32 + lane]);
                acc.x += w0 * v0.x;
                acc.y += w0 * v0.y;
            }
        } else {
            acc.x = 0.0f; acc.y = 0.0f;
        }
        __half2 h = __floats2half2_rn(acc.x, acc.y);
        As_u[j * (LDA1 / 2) + lane] = *(unsigned*)&h;
    }
    __syncthreads();

    // phase 2: HMMA GEMM (64x64) x (64x128)
    const int mt = w >> 1;
    const int nh = w & 1;
    float acc[8][4];
#pragma unroll
    for (int i = 0; i < 8; ++i)
#pragma unroll
        for (int jj = 0; jj < 4; ++jj) acc[i][jj] = 0.0f;

    mma_gemm_phase<C_IN, LDA1>(s2u(As), s2u(Wh), lane, mt, nh, acc);

    // epilogue: bias + relu -> fp16 store
    const int gid = lane >> 2, tig = lane & 3;
#pragma unroll
    for (int nt = 0; nt < 8; ++nt) {
        int col = nh * 64 + nt * 8 + tig * 2;
        float b0v = __ldg(&bias[col]);
        float b1v = __ldg(&bias[col + 1]);
        int r0 = node_base + mt * 16 + gid;
        int r1 = r0 + 8;
        if (r0 < NN) {
            __half2 h = __floats2half2_rn(fmaxf(acc[nt][0] + b0v, 0.0f),
                                          fmaxf(acc[nt][1] + b1v, 0.0f));
            ((unsigned*)g_h1h)[(size_t)r0 * 64 + (col >> 1)] = *(unsigned*)&h;
        }
        if (r1 < NN) {
            __half2 h = __floats2half2_rn(fmaxf(acc[nt][2] + b0v, 0.0f),
                                          fmaxf(acc[nt][3] + b1v, 0.0f));
            ((unsigned*)g_h1h)[(size_t)r1 * 64 + (col >> 1)] = *(unsigned*)&h;
        }
    }
}

// ---------------- fused layer 2: 128-row tile, 512 threads ----------------
// gather-agg(H1h,128) + HMMA GEMM W2 + relu + mean-pool
#define LDA2 136                      // halves (row = 272B)
#define F2_AS_B   (128 * LDA2 * 2)    // 34816
#define F2_W_B    (128 * 136 * 2)     // 34816
#define F2_SBAT_B (128 * 4)
#define F2_SMEM   (F2_AS_B + F2_W_B + F2_SBAT_B)   // 70144; out[128][128]f32 (64KB) overlays As+W

__global__ __launch_bounds__(512)
void k_fused2(const float* __restrict__ bias, const void* __restrict__ batch) {
    extern __shared__ char smb[];
    __half* As = (__half*)smb;
    __half* Wh = (__half*)(smb + F2_AS_B);
    float*  out = (float*)smb;                       // reused after GEMM
    int*    sbat = (int*)(smb + F2_AS_B + F2_W_B);

    const int tid = threadIdx.x;
    const int lane = tid & 31;
    const int w = tid >> 5;                          // 0..15
    const int node_base = blockIdx.x * 128;
    const int lim = min(128, NN - node_base);
    const uint2* __restrict__ Hu = (const uint2*)g_h1h;
    const int2* __restrict__ E = g_edge;
    uint2* As_u2 = (uint2*)As;

    if (tid < 128) {
        int n = node_base + tid;
        int g = 0;
        if (n < NN) g = read_idx(batch, n);
        sbat[tid] = min(max(g, 0), NG - 1);
    }

    // load W2 fp16 into padded smem [128][136]
#pragma unroll
    for (int it = 0; it < 4; ++it) {
        int idx = tid + it * 512;              // uint4 chunks: 2048 total
        int row = idx >> 4, ch = idx & 15;
        uint4 v = ((const uint4*)g_w2h)[idx];
        *(uint4*)&Wh[row * 136 + ch * 8] = v;
    }

    // phase 1: warp-per-node gather aggregation, unroll 4
    for (int j = w; j < 128; j += 16) {
        int node = node_base + j;
        float4 acc;
        if (node < NN) {
            float di = g_dinv[node];
            float sw = di * di;
            uint2 su = Hu[(size_t)node * 32 + lane];
            float2 sa = h2f(su.x), sb = h2f(su.y);
            acc = make_float4(sa.x * sw, sa.y * sw, sb.x * sw, sb.y * sw);
            int beg = g_off[node];
            int cnt = g_degi[node];
            int k = 0;
            for (; k + 4 <= cnt; k += 4) {
                int2 e0 = E[beg + k];
                int2 e1 = E[beg + k + 1];
                int2 e2 = E[beg + k + 2];
                int2 e3 = E[beg + k + 3];
                uint2 u0 = Hu[(size_t)e0.x * 32 + lane];
                uint2 u1 = Hu[(size_t)e1.x * 32 + lane];
                uint2 u2 = Hu[(size_t)e2.x * 32 + lane];
                uint2 u3 = Hu[(size_t)e3.x * 32 + lane];
                float w0 = __int_as_float(e0.y);
                float w1 = __int_as_float(e1.y);
                float w2 = __int_as_float(e2.y);
                float w3 = __int_as_float(e3.y);
                float2 a0 = h2f(u0.x), b0 = h2f(u0.y);
                float2 a1 = h2f(u1.x), b1 = h2f(u1.y);
                float2 a2 = h2f(u2.x), b2 = h2f(u2.y);
                float2 a3 = h2f(u3.x), b3 = h2f(u3.y);
                acc.x += w0 * a0.x + w1 * a1.x + w2 * a2.x + w3 * a3.x;
                acc.y += w0 * a0.y + w1 * a1.y + w2 * a2.y + w3 * a3.y;
                acc.z += w0 * b0.x + w1 * b1.x + w2 * b2.x + w3 * b3.x;
                acc.w += w0 * b0.y + w1 * b1.y + w2 * b2.y + w3 * b3.y;
            }
            for (; k < cnt; ++k) {
                int2 e0 = E[beg + k];
                float w0 = __int_as_float(e0.y);
                uint2 u0 = Hu[(size_t)e0.x * 32 + lane];
                float2 a0 = h2f(u0.x), b0 = h2f(u0.y);
                acc.x += w0 * a0.x;
                acc.y += w0 * a0.y;
                acc.z += w0 * b0.x;
                acc.w += w0 * b0.y;
            }
        } else {
            acc = make_float4(0.0f, 0.0f, 0.0f, 0.0f);
        }
        __half2 h0 = __floats2half2_rn(acc.x, acc.y);
        __half2 h1 = __floats2half2_rn(acc.z, acc.w);
        uint2 u;
        u.x = *(unsigned*)&h0;
        u.y = *(unsigned*)&h1;
        As_u2[j * (LDA2 / 4) + lane] = u;
    }
    __syncthreads();

    // phase 2: HMMA GEMM (128x128) x (128x128); 16 warps: mt 0..7, nh 0..1
    const int mt = w >> 1;
    const int nh = w & 1;
    float acc[8][4];
#pragma unroll
    for (int i = 0; i < 8; ++i)
#pragma unroll
        for (int jj = 0; jj < 4; ++jj) acc[i][jj] = 0.0f;

    mma_gemm_phase<C_HID, LDA2>(s2u(As), s2u(Wh), lane, mt, nh, acc);
    __syncthreads();   // all reads of As/Wh done before overlaying `out`

    // phase 3: bias + relu into smem out[128][128]
    const int gid = lane >> 2, tig = lane & 3;
    const int r0l = mt * 16 + gid, r1l = r0l + 8;
#pragma unroll
    for (int nt = 0; nt < 8; ++nt) {
        int col = nh * 64 + nt * 8 + tig * 2;
        float b0v = __ldg(&bias[col]);
        float b1v = __ldg(&bias[col + 1]);
        out[r0l * 128 + col]     = fmaxf(acc[nt][0] + b0v, 0.0f);
        out[r0l * 128 + col + 1] = fmaxf(acc[nt][1] + b1v, 0.0f);
        out[r1l * 128 + col]     = fmaxf(acc[nt][2] + b0v, 0.0f);
        out[r1l * 128 + col + 1] = fmaxf(acc[nt][3] + b1v, 0.0f);
    }
    __syncthreads();

    // phase 4: per-column pooled reduction over sorted batch ids
    if (tid < 128 && lim > 0) {
        int c = tid;
        float accp = 0.0f;
        int g = sbat[0];
        for (int r = 0; r < lim; ++r) {
            int gb = sbat[r];
            if (gb != g) {
                atomicAdd(&g_pooled[g * C_HID + c], accp);
                g = gb; accp = 0.0f;
            }
            accp += out[r * 128 + c];
        }
        atomicAdd(&g_pooled[g * C_HID + c], accp);
    }
}

// ---------------- classifier head: one block per graph, warp-reduced dots ----------------
__global__ __launch_bounds__(32) void k_final(const float* __restrict__ Wc,
                                              const float* __restrict__ bc,
                                              float* __restrict__ out) {
    int g = blockIdx.x;
    int lane = threadIdx.x;
    float inv = 1.0f / fmaxf(g_cnt[g], 1.0f);
    float p[4];
#pragma unroll
    for (int i = 0; i < 4; ++i) p[i] = g_pooled[g * C_HID + i * 32 + lane];
#pragma unroll
    for (int c = 0; c < NC; ++c) {
        float s = 0.0f;
#pragma unroll
        for (int i = 0; i < 4; ++i)
            s += p[i] * __ldg(&Wc[(i * 32 + lane) * NC + c]);
#pragma unroll
        for (int o = 16; o > 0; o >>= 1)
            s += __shfl_down_sync(0xFFFFFFFFu, s, o);
        if (lane == 0) out[g * NC + c] = s * inv + bc[c];
    }
}

// ---------------- launch ----------------
extern "C" void kernel_launch(void* const* d_in, const int* in_sizes, int n_in,
                              void* d_out, int out_size) {
    const float* x = 0; const float* W1 = 0; const float* b1 = 0;
    const float* W2 = 0; const float* b2 = 0; const float* Wc = 0;
    const float* bc = 0; const void* ei = 0; const void* batch = 0;
    for (int i = 0; i < n_in; ++i) {
        int s = in_sizes[i];
        void* p = d_in[i];
        if      (s == NN * C_IN)     x  = (const float*)p;
        else if (s == C_IN * C_HID)  W1 = (const float*)p;
        else if (s == C_HID * C_HID) W2 = (const float*)p;
        else if (s == C_HID * NC)    Wc = (const float*)p;
        else if (s == NC)            bc = (const float*)p;
        else if (s == 2 * NE)        ei = p;
        else if (s == NN)            batch = p;
        else if (s == C_HID)         { if (!b1) b1 = (const float*)p; else b2 = (const float*)p; }
    }
    if (!b2) b2 = b1;
    float* out = (float*)d_out;
    (void)out_size;

    static int attr_done = 0;
    if (!attr_done) {
        cudaFuncSetAttribute(k_fused2, cudaFuncAttributeMaxDynamicSharedMemorySize, F2_SMEM);
        attr_done = 1;
    }

    const int T = 256;
    const int CVT_BLKS = (NT_X + NT_W1 + NT_W2 + T - 1) / T;

    k_init<<<NBLK, T>>>(ei);                              // 0 (zero + dtype detect)
    k_convert<<<CVT_BLKS, T>>>(x, W1, W2);                // 1
    k_edge_prep<<<(NE + T - 1) / T, T>>>(ei);             // 2
    k_blocksum<<<NBLK, T>>>(batch);                       // 3 (scan sums + batch histogram)
    k_offsets<<<NBLK, T>>>();                             // 4 (inline block-prefix)
    k_csr_fill<<<(NE + T - 1) / T, T>>>();                // 5 (no atomics)

    k_fused1<<<NTILE1, T>>>(b1);                          // 6
    k_fused2<<<NTILE2, 512, F2_SMEM>>>(b2, batch);        // 7
    k_final<<<NG, 32>>>(Wc, bc, out);                     // 8
}

// round 16
// speedup vs baseline: 1.0193x; 1.0193x over previous
#include <cuda_runtime.h>
#include <cuda_fp16.h>

#define NN 100000
#define NE 1600000
#define C_IN 64
#define C_HID 128
#define NG 64
#define NC 10
#define NBLK ((NN + 255) / 256)    // 391
#define NTILE ((NN + 63) / 64)     // 1563

// ---------------- scratch (__device__ globals; no allocations) ----------------
static __device__ __align__(16) int    g_degi[NN];
static __device__ __align__(16) int    g_off[NN];
static __device__ __align__(16) float  g_dinv[NN];
static __device__ __align__(16) int    g_bsum[NBLK];
static __device__ __align__(16) int2   g_sd[NE];       // {src, dst | rank<<17}
static __device__ __align__(16) int2   g_edge[NE];     // CSR payload: {src, norm-bits}
static __device__ __align__(16) __half g_xh[(size_t)NN * C_IN];    // 12.8 MB
static __device__ __align__(16) __half g_h1h[(size_t)NN * C_HID];  // 25.6 MB
static __device__ __align__(16) __half g_w1h[C_IN * C_HID];
static __device__ __align__(16) __half g_w2h[C_HID * C_HID];
static __device__ __align__(16) float  g_pooled[NG * C_HID];
static __device__ __align__(16) float  g_cnt[NG];
static __device__ int g_is64;

__device__ __forceinline__ int read_idx(const void* p, long long i) {
    if (g_is64) return (int)((const long long*)p)[i];
    return ((const int*)p)[i];
}
__device__ __forceinline__ float2 h2f(unsigned u) {
    __half2 h = *(__half2*)&u;
    return __half22float2(h);
}
__device__ __forceinline__ unsigned s2u(const void* p) {
    return (unsigned)__cvta_generic_to_shared(p);
}

// ---------------- mma / ldmatrix helpers ----------------
__device__ __forceinline__ void mma_f16(float c[4], unsigned a0, unsigned a1,
                                        unsigned a2, unsigned a3,
                                        unsigned b0, unsigned b1) {
    asm volatile(
        "mma.sync.aligned.m16n8k16.row.col.f32.f16.f16.f32 "
        "{%0,%1,%2,%3}, {%4,%5,%6,%7}, {%8,%9}, {%0,%1,%2,%3};"
        : "+f"(c[0]), "+f"(c[1]), "+f"(c[2]), "+f"(c[3])
        : "r"(a0), "r"(a1), "r"(a2), "r"(a3), "r"(b0), "r"(b1));
}
__device__ __forceinline__ void ldsm_x4(unsigned& r0, unsigned& r1, unsigned& r2,
                                        unsigned& r3, unsigned addr) {
    asm volatile("ldmatrix.sync.aligned.m8n8.x4.shared.b16 {%0,%1,%2,%3}, [%4];"
                 : "=r"(r0), "=r"(r1), "=r"(r2), "=r"(r3) : "r"(addr));
}
__device__ __forceinline__ void ldsm_x4_t(unsigned& r0, unsigned& r1, unsigned& r2,
                                          unsigned& r3, unsigned addr) {
    asm volatile("ldmatrix.sync.aligned.m8n8.x4.trans.shared.b16 {%0,%1,%2,%3}, [%4];"
                 : "=r"(r0), "=r"(r1), "=r"(r2), "=r"(r3) : "r"(addr));
}

// GEMM phase: acc[8][4] += As[mt*16..+16, 0..K) x W[0..K, nh*64..+64)
template<int K, int LDA>
__device__ __forceinline__ void mma_gemm_phase(unsigned asb, unsigned wb, int lane,
                                               int mt, int nh, float acc[8][4]) {
    const int m0 = mt * 16;
    unsigned a_base = asb + (((m0 + (lane & 15)) * LDA) + ((lane >> 4) << 3)) * 2;
    const int brow = (lane & 7) + (lane & 8);
    const int bcol = nh * 64 + ((lane & 16) >> 1);
#pragma unroll
    for (int k0 = 0; k0 < K; k0 += 16) {
        unsigned a0, a1, a2, a3;
        ldsm_x4(a0, a1, a2, a3, a_base + k0 * 2);
#pragma unroll
        for (int p = 0; p < 4; ++p) {
            unsigned b0, b1, b2, b3;
            unsigned baddr = wb + (((k0 + brow) * 136) + bcol + p * 16) * 2;
            ldsm_x4_t(b0, b1, b2, b3, baddr);
            mma_f16(acc[2 * p],     a0, a1, a2, a3, b0, b1);
            mma_f16(acc[2 * p + 1], a0, a1, a2, a3, b2, b3);
        }
    }
}

// ---------------- init (zero) + dtype detect (block 0 thread 0) ----------------
__global__ __launch_bounds__(256) void k_init(const void* __restrict__ ei) {
    int t = blockIdx.x * 256 + threadIdx.x;
    if (t == 0) {
        const long long* p = (const long long*)ei;
        int ok64 = 1;
        for (int i = 0; i < 64; ++i) {
            long long v = p[i];
            if (v < 0 || v >= NN) { ok64 = 0; break; }
        }
        g_is64 = ok64;
    }
    if (t < NN) g_degi[t] = 0;
    if (t < NG * C_HID) g_pooled[t] = 0.0f;
    if (t < NG) g_cnt[t] = 0.0f;
}

// ---------------- fp16 conversions: x, W1, W2 in one kernel ----------------
#define NT_X  (NN * C_IN / 4)          // float4 items: 1,600,000
#define NT_W1 (C_IN * C_HID / 2)       // half2 items:  4096
#define NT_W2 (C_HID * C_HID / 2)      // half2 items:  8192
__global__ __launch_bounds__(256)
void k_convert(const float* __restrict__ X, const float* __restrict__ W1,
               const float* __restrict__ W2) {
    int i = blockIdx.x * 256 + threadIdx.x;
    if (i < NT_X) {
        float4 v = ((const float4*)X)[i];
        __half2 a = __floats2half2_rn(v.x, v.y);
        __half2 b = __floats2half2_rn(v.z, v.w);
        uint2 u;
        u.x = *(unsigned*)&a;
        u.y = *(unsigned*)&b;
        ((uint2*)g_xh)[i] = u;
    } else if (i < NT_X + NT_W1) {
        int j = i - NT_X;
        float2 v = ((const float2*)W1)[j];
        ((__half2*)g_w1h)[j] = __floats2half2_rn(v.x, v.y);
    } else if (i < NT_X + NT_W1 + NT_W2) {
        int j = i - NT_X - NT_W1;
        float2 v = ((const float2*)W2)[j];
        ((__half2*)g_w2h)[j] = __floats2half2_rn(v.x, v.y);
    }
}

// ---------------- edge prep: decode once, count degrees, capture rank ----------------
__global__ void k_edge_prep(const void* __restrict__ ei) {
    int e = blockIdx.x * blockDim.x + threadIdx.x;
    if (e >= NE) return;
    int s = read_idx(ei, e);
    int d = read_idx(ei, (long long)NE + e);
    s = min(max(s, 0), NN - 1);
    d = min(max(d, 0), NN - 1);
    int rank = atomicAdd(&g_degi[d], 1);       // within-row rank for free
    if (rank > 32767) rank = 32767;            // defensive (never hit for this data)
    g_sd[e] = make_int2(s, d | (rank << 17));  // dst < 2^17
}

// ---- block sums for scan + batch histogram (g_cnt zeroed in EARLIER kernel) ----
__global__ __launch_bounds__(256) void k_blocksum(const void* __restrict__ batch) {
    __shared__ int ws[8];
    __shared__ int h[NG];
    if (threadIdx.x < NG) h[threadIdx.x] = 0;
    int i = blockIdx.x * 256 + threadIdx.x;
    int v = (i < NN) ? g_degi[i] : 0;
    int lane = threadIdx.x & 31, wid = threadIdx.x >> 5;
#pragma unroll
    for (int o = 16; o > 0; o >>= 1) v += __shfl_down_sync(0xFFFFFFFFu, v, o);
    if (lane == 0) ws[wid] = v;
    __syncthreads();
    if (threadIdx.x == 0) {
        int s = 0;
#pragma unroll
        for (int w = 0; w < 8; ++w) s += ws[w];
        g_bsum[blockIdx.x] = s;
    }
    if (i < NN) {
        int g = read_idx(batch, i);
        g = min(max(g, 0), NG - 1);
        atomicAdd(&h[g], 1);
    }
    __syncthreads();
    if (threadIdx.x < NG && h[threadIdx.x] > 0)
        atomicAdd(&g_cnt[threadIdx.x], (float)h[threadIdx.x]);
}

// ---- offsets: inline exclusive block-prefix (sum g_bsum[0..bid)) + in-block scan ----
__global__ __launch_bounds__(256) void k_offsets() {
    __shared__ int ws2[8];
    __shared__ int ws[8];
    __shared__ int s_boff;
    int lane = threadIdx.x & 31, wid = threadIdx.x >> 5;

    int partial = 0;
    for (int i = threadIdx.x; i < blockIdx.x; i += 256) partial += g_bsum[i];
#pragma unroll
    for (int o = 16; o > 0; o >>= 1) partial += __shfl_down_sync(0xFFFFFFFFu, partial, o);
    if (lane == 0) ws2[wid] = partial;
    __syncthreads();
    if (threadIdx.x == 0) {
        int s = 0;
#pragma unroll
        for (int w = 0; w < 8; ++w) s += ws2[w];
        s_boff = s;
    }

    int i = blockIdx.x * 256 + threadIdx.x;
    int deg = (i < NN) ? g_degi[i] : 0;
    int v = deg;
#pragma unroll
    for (int o = 1; o < 32; o <<= 1) {
        int t = __shfl_up_sync(0xFFFFFFFFu, v, o);
        if (lane >= o) v += t;
    }
    if (lane == 31) ws[wid] = v;
    __syncthreads();
    if (wid == 0 && lane < 8) {
        int w = ws[lane];
#pragma unroll
        for (int o = 1; o < 8; o <<= 1) {
            int t = __shfl_up_sync(0xFFu, w, o);
            if (lane >= o) w += t;
        }
        ws[lane] = w;
    }
    __syncthreads();
    int excl = v - deg + (wid > 0 ? ws[wid - 1] : 0) + s_boff;
    if (i < NN) {
        g_off[i] = excl;
        g_dinv[i] = rsqrtf((float)(deg + 1));
    }
}

// fill CSR payload from decoded pairs — no atomics (rank precomputed)
__global__ void k_csr_fill() {
    int e = blockIdx.x * blockDim.x + threadIdx.x;
    if (e >= NE) return;
    int2 sd = g_sd[e];
    int d = sd.y & 0x1FFFF;
    int rank = ((unsigned)sd.y) >> 17;
    int pos = g_off[d] + rank;
    float nrm = g_dinv[sd.x] * g_dinv[d];
    g_edge[pos] = make_int2(sd.x, __float_as_int(nrm));
}

// ---------------- fused layer 1: gather-agg(x_h,64) + HMMA GEMM W1 + relu -> H1(fp16) ----------------
#define LDA1 72    // halves (row = 144B)
__global__ __launch_bounds__(256)
void k_fused1(const float* __restrict__ bias) {
    __shared__ __half As[64 * LDA1];     // 9.2 KB
    __shared__ __half Wh[64 * 136];      // 17.4 KB

    const int tid = threadIdx.x;
    const int lane = tid & 31;
    const int w = tid >> 5;
    const int node_base = blockIdx.x * 64;
    const unsigned* __restrict__ Xu = (const unsigned*)g_xh;
    const int2* __restrict__ E = g_edge;
    unsigned* As_u = (unsigned*)As;

    // load W1 fp16 into padded smem [64][136]
#pragma unroll
    for (int it = 0; it < 4; ++it) {
        int idx = tid + it * 256;              // uint4 chunks: 1024 total
        int row = idx >> 4, ch = idx & 15;
        uint4 v = ((const uint4*)g_w1h)[idx];
        *(uint4*)&Wh[row * 136 + ch * 8] = v;
    }

    // phase 1: warp-per-node gather aggregation, unroll 4
    for (int j = w; j < 64; j += 8) {
        int node = node_base + j;
        float2 acc;
        if (node < NN) {
            float di = g_dinv[node];
            float sw = di * di;
            acc = h2f(Xu[node * 32 + lane]);
            acc.x *= sw; acc.y *= sw;
            int beg = g_off[node];
            int cnt = g_degi[node];
            int k = 0;
            for (; k + 4 <= cnt; k += 4) {
                int2 e0 = E[beg + k];
                int2 e1 = E[beg + k + 1];
                int2 e2 = E[beg + k + 2];
                int2 e3 = E[beg + k + 3];
                float2 v0 = h2f(Xu[e0.x * 32 + lane]);
                float2 v1 = h2f(Xu[e1.x * 32 + lane]);
                float2 v2 = h2f(Xu[e2.x * 32 + lane]);
                float2 v3 = h2f(Xu[e3.x * 32 + lane]);
                float w0 = __int_as_float(e0.y);
                float w1 = __int_as_float(e1.y);
                float w2 = __int_as_float(e2.y);
                float w3 = __int_as_float(e3.y);
                acc.x += w0 * v0.x + w1 * v1.x + w2 * v2.x + w3 * v3.x;
                acc.y += w0 * v0.y + w1 * v1.y + w2 * v2.y + w3 * v3.y;
            }
            for (; k < cnt; ++k) {
                int2 e0 = E[beg + k];
                float w0 = __int_as_float(e0.y);
                float2 v0 = h2f(Xu[e0.x * 32 + lane]);
                acc.x += w0 * v0.x;
                acc.y += w0 * v0.y;
            }
        } else {
            acc.x = 0.0f; acc.y = 0.0f;
        }
        __half2 h = __floats2half2_rn(acc.x, acc.y);
        As_u[j * (LDA1 / 2) + lane] = *(unsigned*)&h;
    }
    __syncthreads();

    // phase 2: HMMA GEMM (64x64) x (64x128)
    const int mt = w >> 1;
    const int nh = w & 1;
    float acc[8][4];
#pragma unroll
    for (int i = 0; i < 8; ++i)
#pragma unroll
        for (int jj = 0; jj < 4; ++jj) acc[i][jj] = 0.0f;

    mma_gemm_phase<C_IN, LDA1>(s2u(As), s2u(Wh), lane, mt, nh, acc);

    // epilogue: bias + relu -> fp16 store
    const int gid = lane >> 2, tig = lane & 3;
#pragma unroll
    for (int nt = 0; nt < 8; ++nt) {
        int col = nh * 64 + nt * 8 + tig * 2;
        float b0v = __ldg(&bias[col]);
        float b1v = __ldg(&bias[col + 1]);
        int r0 = node_base + mt * 16 + gid;
        int r1 = r0 + 8;
        if (r0 < NN) {
            __half2 h = __floats2half2_rn(fmaxf(acc[nt][0] + b0v, 0.0f),
                                          fmaxf(acc[nt][1] + b1v, 0.0f));
            ((unsigned*)g_h1h)[(size_t)r0 * 64 + (col >> 1)] = *(unsigned*)&h;
        }
        if (r1 < NN) {
            __half2 h = __floats2half2_rn(fmaxf(acc[nt][2] + b0v, 0.0f),
                                          fmaxf(acc[nt][3] + b1v, 0.0f));
            ((unsigned*)g_h1h)[(size_t)r1 * 64 + (col >> 1)] = *(unsigned*)&h;
        }
    }
}

// ---------------- fused layer 2: 64-row tile, 256 threads (proven config) ----------------
// gather-agg(H1h,128) + HMMA GEMM W2 + relu + mean-pool
#define LDA2 136                    // halves (row = 272B)
#define F2_AS_B   (64 * LDA2 * 2)   // 17408
#define F2_W_B    (128 * 136 * 2)   // 34816
#define F2_SBAT_B (64 * 4)
#define F2_SMEM   (F2_AS_B + F2_W_B + F2_SBAT_B)   // 52480; out[64][128]f32 overlays As+W

__global__ __launch_bounds__(256)
void k_fused2(const float* __restrict__ bias, const void* __restrict__ batch) {
    extern __shared__ char smb[];
    __half* As = (__half*)smb;
    __half* Wh = (__half*)(smb + F2_AS_B);
    float*  out = (float*)smb;                       // reused after GEMM
    int*    sbat = (int*)(smb + F2_AS_B + F2_W_B);

    const int tid = threadIdx.x;
    const int lane = tid & 31;
    const int w = tid >> 5;
    const int node_base = blockIdx.x * 64;
    const int lim = min(64, NN - node_base);
    const uint2* __restrict__ Hu = (const uint2*)g_h1h;
    const int2* __restrict__ E = g_edge;
    uint2* As_u2 = (uint2*)As;

    if (tid < 64) {
        int n = node_base + tid;
        int g = 0;
        if (n < NN) g = read_idx(batch, n);
        sbat[tid] = min(max(g, 0), NG - 1);
    }

    // load W2 fp16 into padded smem [128][136]
#pragma unroll
    for (int it = 0; it < 8; ++it) {
        int idx = tid + it * 256;              // uint4 chunks: 2048 total
        int row = idx >> 4, ch = idx & 15;
        uint4 v = ((const uint4*)g_w2h)[idx];
        *(uint4*)&Wh[row * 136 + ch * 8] = v;
    }

    // phase 1: warp-per-node gather aggregation, unroll 4
    for (int j = w; j < 64; j += 8) {
        int node = node_base + j;
        float4 acc;
        if (node < NN) {
            float di = g_dinv[node];
            float sw = di * di;
            uint2 su = Hu[(size_t)node * 32 + lane];
            float2 sa = h2f(su.x), sb = h2f(su.y);
            acc = make_float4(sa.x * sw, sa.y * sw, sb.x * sw, sb.y * sw);
            int beg = g_off[node];
            int cnt = g_degi[node];
            int k = 0;
            for (; k + 4 <= cnt; k += 4) {
                int2 e0 = E[beg + k];
                int2 e1 = E[beg + k + 1];
                int2 e2 = E[beg + k + 2];
                int2 e3 = E[beg + k + 3];
                uint2 u0 = Hu[(size_t)e0.x * 32 + lane];
                uint2 u1 = Hu[(size_t)e1.x * 32 + lane];
                uint2 u2 = Hu[(size_t)e2.x * 32 + lane];
                uint2 u3 = Hu[(size_t)e3.x * 32 + lane];
                float w0 = __int_as_float(e0.y);
                float w1 = __int_as_float(e1.y);
                float w2 = __int_as_float(e2.y);
                float w3 = __int_as_float(e3.y);
                float2 a0 = h2f(u0.x), b0 = h2f(u0.y);
                float2 a1 = h2f(u1.x), b1 = h2f(u1.y);
                float2 a2 = h2f(u2.x), b2 = h2f(u2.y);
                float2 a3 = h2f(u3.x), b3 = h2f(u3.y);
                acc.x += w0 * a0.x + w1 * a1.x + w2 * a2.x + w3 * a3.x;
                acc.y += w0 * a0.y + w1 * a1.y + w2 * a2.y + w3 * a3.y;
                acc.z += w0 * b0.x + w1 * b1.x + w2 * b2.x + w3 * b3.x;
                acc.w += w0 * b0.y + w1 * b1.y + w2 * b2.y + w3 * b3.y;
            }
            for (; k < cnt; ++k) {
                int2 e0 = E[beg + k];
                float w0 = __int_as_float(e0.y);
                uint2 u0 = Hu[(size_t)e0.x * 32 + lane];
                float2 a0 = h2f(u0.x), b0 = h2f(u0.y);
                acc.x += w0 * a0.x;
                acc.y += w0 * a0.y;
                acc.z += w0 * b0.x;
                acc.w += w0 * b0.y;
            }
        } else {
            acc = make_float4(0.0f, 0.0f, 0.0f, 0.0f);
        }
        __half2 h0 = __floats2half2_rn(acc.x, acc.y);
        __half2 h1 = __floats2half2_rn(acc.z, acc.w);
        uint2 u;
        u.x = *(unsigned*)&h0;
        u.y = *(unsigned*)&h1;
        As_u2[j * (LDA2 / 4) + lane] = u;
    }
    __syncthreads();

    // phase 2: HMMA GEMM (64x128) x (128x128)
    const int mt = w >> 1;
    const int nh = w & 1;
    float acc[8][4];
#pragma unroll
    for (int i = 0; i < 8; ++i)
#pragma unroll
        for (int jj = 0; jj < 4; ++jj) acc[i][jj] = 0.0f;

    mma_gemm_phase<C_HID, LDA2>(s2u(As), s2u(Wh), lane, mt, nh, acc);
    __syncthreads();   // all reads of As/Wh done before overlaying `out`

    // phase 3: bias + relu into smem out[64][128]
    const int gid = lane >> 2, tig = lane & 3;
    const int r0l = mt * 16 + gid, r1l = r0l + 8;
#pragma unroll
    for (int nt = 0; nt < 8; ++nt) {
        int col = nh * 64 + nt * 8 + tig * 2;
        float b0v = __ldg(&bias[col]);
        float b1v = __ldg(&bias[col + 1]);
        out[r0l * 128 + col]     = fmaxf(acc[nt][0] + b0v, 0.0f);
        out[r0l * 128 + col + 1] = fmaxf(acc[nt][1] + b1v, 0.0f);
        out[r1l * 128 + col]     = fmaxf(acc[nt][2] + b0v, 0.0f);
        out[r1l * 128 + col + 1] = fmaxf(acc[nt][3] + b1v, 0.0f);
    }
    __syncthreads();

    // phase 4: per-column pooled reduction over sorted batch ids
    if (tid < 128 && lim > 0) {
        int c = tid;
        float accp = 0.0f;
        int g = sbat[0];
        for (int r = 0; r < lim; ++r) {
            int gb = sbat[r];
            if (gb != g) {
                atomicAdd(&g_pooled[g * C_HID + c], accp);
                g = gb; accp = 0.0f;
            }
            accp += out[r * 128 + c];
        }
        atomicAdd(&g_pooled[g * C_HID + c], accp);
    }
}

// ---------------- classifier head: one block per graph, warp-reduced dots ----------------
__global__ __launch_bounds__(32) void k_final(const float* __restrict__ Wc,
                                              const float* __restrict__ bc,
                                              float* __restrict__ out) {
    int g = blockIdx.x;
    int lane = threadIdx.x;
    float inv = 1.0f / fmaxf(g_cnt[g], 1.0f);
    float p[4];
#pragma unroll
    for (int i = 0; i < 4; ++i) p[i] = g_pooled[g * C_HID + i * 32 + lane];
#pragma unroll
    for (int c = 0; c < NC; ++c) {
        float s = 0.0f;
#pragma unroll
        for (int i = 0; i < 4; ++i)
            s += p[i] * __ldg(&Wc[(i * 32 + lane) * NC + c]);
#pragma unroll
        for (int o = 16; o > 0; o >>= 1)
            s += __shfl_down_sync(0xFFFFFFFFu, s, o);
        if (lane == 0) out[g * NC + c] = s * inv + bc[c];
    }
}

// ---------------- launch ----------------
extern "C" void kernel_launch(void* const* d_in, const int* in_sizes, int n_in,
                              void* d_out, int out_size) {
    const float* x = 0; const float* W1 = 0; const float* b1 = 0;
    const float* W2 = 0; const float* b2 = 0; const float* Wc = 0;
    const float* bc = 0; const void* ei = 0; const void* batch = 0;
    for (int i = 0; i < n_in; ++i) {
        int s = in_sizes[i];
        void* p = d_in[i];
        if      (s == NN * C_IN)     x  = (const float*)p;
        else if (s == C_IN * C_HID)  W1 = (const float*)p;
        else if (s == C_HID * C_HID) W2 = (const float*)p;
        else if (s == C_HID * NC)    Wc = (const float*)p;
        else if (s == NC)            bc = (const float*)p;
        else if (s == 2 * NE)        ei = p;
        else if (s == NN)            batch = p;
        else if (s == C_HID)         { if (!b1) b1 = (const float*)p; else b2 = (const float*)p; }
    }
    if (!b2) b2 = b1;
    float* out = (float*)d_out;
    (void)out_size;

    static int attr_done = 0;
    if (!attr_done) {
        cudaFuncSetAttribute(k_fused2, cudaFuncAttributeMaxDynamicSharedMemorySize, F2_SMEM);
        attr_done = 1;
    }

    const int T = 256;
    const int CVT_BLKS = (NT_X + NT_W1 + NT_W2 + T - 1) / T;

    k_init<<<NBLK, T>>>(ei);                              // 0 (zero + dtype detect)
    k_convert<<<CVT_BLKS, T>>>(x, W1, W2);                // 1
    k_edge_prep<<<(NE + T - 1) / T, T>>>(ei);             // 2
    k_blocksum<<<NBLK, T>>>(batch);                       // 3 (scan sums + batch histogram)
    k_offsets<<<NBLK, T>>>();                             // 4 (inline block-prefix)
    k_csr_fill<<<(NE + T - 1) / T, T>>>();                // 5 (no atomics)

    k_fused1<<<NTILE, T>>>(b1);                           // 6
    k_fused2<<<NTILE, T, F2_SMEM>>>(b2, batch);           // 7
    k_final<<<NG, 32>>>(Wc, bc, out);                     // 8
}

// round 17
// speedup vs baseline: 1.1222x; 1.1009x over previous
#include <cuda_runtime.h>
#include <cuda_fp16.h>

#define NN 100000
#define NE 1600000
#define C_IN 64
#define C_HID 128
#define NG 64
#define NC 10
#define NBLK ((NN + 255) / 256)    // 391
#define NTILE ((NN + 63) / 64)     // 1563

// ---------------- scratch (__device__ globals; no allocations) ----------------
static __device__ __align__(16) int    g_degi[NN];
static __device__ __align__(16) int    g_off[NN];
static __device__ __align__(16) float  g_dinv[NN];
static __device__ __align__(16) int    g_bsum[NBLK];
static __device__ __align__(16) int2   g_sd[NE];       // {src, dst | rank<<17}
static __device__ __align__(16) int    g_csrc[NE];     // CSR: src only (features pre-scaled)
static __device__ __align__(16) __half g_xh[(size_t)NN * C_IN];    // dinv-scaled x, fp16
static __device__ __align__(16) __half g_h1h[(size_t)NN * C_HID];  // dinv-scaled H1, fp16
static __device__ __align__(16) __half g_w1h[C_IN * C_HID];
static __device__ __align__(16) __half g_w2h[C_HID * C_HID];
static __device__ __align__(16) float  g_pooled[NG * C_HID];
static __device__ __align__(16) float  g_cnt[NG];
static __device__ int g_is64;

__device__ __forceinline__ int read_idx(const void* p, long long i) {
    if (g_is64) return (int)((const long long*)p)[i];
    return ((const int*)p)[i];
}
__device__ __forceinline__ float2 h2f(unsigned u) {
    __half2 h = *(__half2*)&u;
    return __half22float2(h);
}
__device__ __forceinline__ unsigned s2u(const void* p) {
    return (unsigned)__cvta_generic_to_shared(p);
}

// ---------------- mma / ldmatrix helpers ----------------
__device__ __forceinline__ void mma_f16(float c[4], unsigned a0, unsigned a1,
                                        unsigned a2, unsigned a3,
                                        unsigned b0, unsigned b1) {
    asm volatile(
        "mma.sync.aligned.m16n8k16.row.col.f32.f16.f16.f32 "
        "{%0,%1,%2,%3}, {%4,%5,%6,%7}, {%8,%9}, {%0,%1,%2,%3};"
        : "+f"(c[0]), "+f"(c[1]), "+f"(c[2]), "+f"(c[3])
        : "r"(a0), "r"(a1), "r"(a2), "r"(a3), "r"(b0), "r"(b1));
}
__device__ __forceinline__ void ldsm_x4(unsigned& r0, unsigned& r1, unsigned& r2,
                                        unsigned& r3, unsigned addr) {
    asm volatile("ldmatrix.sync.aligned.m8n8.x4.shared.b16 {%0,%1,%2,%3}, [%4];"
                 : "=r"(r0), "=r"(r1), "=r"(r2), "=r"(r3) : "r"(addr));
}
__device__ __forceinline__ void ldsm_x4_t(unsigned& r0, unsigned& r1, unsigned& r2,
                                          unsigned& r3, unsigned addr) {
    asm volatile("ldmatrix.sync.aligned.m8n8.x4.trans.shared.b16 {%0,%1,%2,%3}, [%4];"
                 : "=r"(r0), "=r"(r1), "=r"(r2), "=r"(r3) : "r"(addr));
}

// full-W GEMM phase (fused1): acc += As[mt*16..+16, 0..K) x W[0..K, nh*64..+64)
template<int K, int LDA>
__device__ __forceinline__ void mma_gemm_phase(unsigned asb, unsigned wb, int lane,
                                               int mt, int nh, float acc[8][4]) {
    const int m0 = mt * 16;
    unsigned a_base = asb + (((m0 + (lane & 15)) * LDA) + ((lane >> 4) << 3)) * 2;
    const int brow = (lane & 7) + (lane & 8);
    const int bcol = nh * 64 + ((lane & 16) >> 1);
#pragma unroll
    for (int k0 = 0; k0 < K; k0 += 16) {
        unsigned a0, a1, a2, a3;
        ldsm_x4(a0, a1, a2, a3, a_base + k0 * 2);
#pragma unroll
        for (int p = 0; p < 4; ++p) {
            unsigned b0, b1, b2, b3;
            unsigned baddr = wb + (((k0 + brow) * 136) + bcol + p * 16) * 2;
            ldsm_x4_t(b0, b1, b2, b3, baddr);
            mma_f16(acc[2 * p],     a0, a1, a2, a3, b0, b1);
            mma_f16(acc[2 * p + 1], a0, a1, a2, a3, b2, b3);
        }
    }
}

// ---------------- init (zero) + dtype detect (block 0 thread 0) ----------------
__global__ __launch_bounds__(256) void k_init(const void* __restrict__ ei) {
    int t = blockIdx.x * 256 + threadIdx.x;
    if (t == 0) {
        const long long* p = (const long long*)ei;
        int ok64 = 1;
        for (int i = 0; i < 64; ++i) {
            long long v = p[i];
            if (v < 0 || v >= NN) { ok64 = 0; break; }
        }
        g_is64 = ok64;
    }
    if (t < NN) g_degi[t] = 0;
    if (t < NG * C_HID) g_pooled[t] = 0.0f;
    if (t < NG) g_cnt[t] = 0.0f;
}

// ---------------- edge prep: decode once, count degrees, capture rank ----------------
__global__ void k_edge_prep(const void* __restrict__ ei) {
    int e = blockIdx.x * blockDim.x + threadIdx.x;
    if (e >= NE) return;
    int s = read_idx(ei, e);
    int d = read_idx(ei, (long long)NE + e);
    s = min(max(s, 0), NN - 1);
    d = min(max(d, 0), NN - 1);
    int rank = atomicAdd(&g_degi[d], 1);
    if (rank > 32767) rank = 32767;
    g_sd[e] = make_int2(s, d | (rank << 17));
}

// ---- block sums for scan + batch histogram ----
__global__ __launch_bounds__(256) void k_blocksum(const void* __restrict__ batch) {
    __shared__ int ws[8];
    __shared__ int h[NG];
    if (threadIdx.x < NG) h[threadIdx.x] = 0;
    int i = blockIdx.x * 256 + threadIdx.x;
    int v = (i < NN) ? g_degi[i] : 0;
    int lane = threadIdx.x & 31, wid = threadIdx.x >> 5;
#pragma unroll
    for (int o = 16; o > 0; o >>= 1) v += __shfl_down_sync(0xFFFFFFFFu, v, o);
    if (lane == 0) ws[wid] = v;
    __syncthreads();
    if (threadIdx.x == 0) {
        int s = 0;
#pragma unroll
        for (int w = 0; w < 8; ++w) s += ws[w];
        g_bsum[blockIdx.x] = s;
    }
    if (i < NN) {
        int g = read_idx(batch, i);
        g = min(max(g, 0), NG - 1);
        atomicAdd(&h[g], 1);
    }
    __syncthreads();
    if (threadIdx.x < NG && h[threadIdx.x] > 0)
        atomicAdd(&g_cnt[threadIdx.x], (float)h[threadIdx.x]);
}

// ---- offsets: inline exclusive block-prefix + in-block scan; writes dinv ----
__global__ __launch_bounds__(256) void k_offsets() {
    __shared__ int ws2[8];
    __shared__ int ws[8];
    __shared__ int s_boff;
    int lane = threadIdx.x & 31, wid = threadIdx.x >> 5;

    int partial = 0;
    for (int i = threadIdx.x; i < blockIdx.x; i += 256) partial += g_bsum[i];
#pragma unroll
    for (int o = 16; o > 0; o >>= 1) partial += __shfl_down_sync(0xFFFFFFFFu, partial, o);
    if (lane == 0) ws2[wid] = partial;
    __syncthreads();
    if (threadIdx.x == 0) {
        int s = 0;
#pragma unroll
        for (int w = 0; w < 8; ++w) s += ws2[w];
        s_boff = s;
    }

    int i = blockIdx.x * 256 + threadIdx.x;
    int deg = (i < NN) ? g_degi[i] : 0;
    int v = deg;
#pragma unroll
    for (int o = 1; o < 32; o <<= 1) {
        int t = __shfl_up_sync(0xFFFFFFFFu, v, o);
        if (lane >= o) v += t;
    }
    if (lane == 31) ws[wid] = v;
    __syncthreads();
    if (wid == 0 && lane < 8) {
        int w = ws[lane];
#pragma unroll
        for (int o = 1; o < 8; o <<= 1) {
            int t = __shfl_up_sync(0xFFu, w, o);
            if (lane >= o) w += t;
        }
        ws[lane] = w;
    }
    __syncthreads();
    int excl = v - deg + (wid > 0 ? ws[wid - 1] : 0) + s_boff;
    if (i < NN) {
        g_off[i] = excl;
        g_dinv[i] = rsqrtf((float)(deg + 1));
    }
}

// ---------------- fp16 conversions (AFTER offsets — x is pre-scaled by dinv) ----------------
#define NT_X  (NN * C_IN / 4)          // float4 items: 1,600,000
#define NT_W1 (C_IN * C_HID / 2)       // half2 items:  4096
#define NT_W2 (C_HID * C_HID / 2)      // half2 items:  8192
__global__ __launch_bounds__(256)
void k_convert(const float* __restrict__ X, const float* __restrict__ W1,
               const float* __restrict__ W2) {
    int i = blockIdx.x * 256 + threadIdx.x;
    if (i < NT_X) {
        float4 v = ((const float4*)X)[i];
        float d = g_dinv[i >> 4];              // 16 float4 chunks per node
        __half2 a = __floats2half2_rn(v.x * d, v.y * d);
        __half2 b = __floats2half2_rn(v.z * d, v.w * d);
        uint2 u;
        u.x = *(unsigned*)&a;
        u.y = *(unsigned*)&b;
        ((uint2*)g_xh)[i] = u;
    } else if (i < NT_X + NT_W1) {
        int j = i - NT_X;
        float2 v = ((const float2*)W1)[j];
        ((__half2*)g_w1h)[j] = __floats2half2_rn(v.x, v.y);
    } else if (i < NT_X + NT_W1 + NT_W2) {
        int j = i - NT_X - NT_W1;
        float2 v = ((const float2*)W2)[j];
        ((__half2*)g_w2h)[j] = __floats2half2_rn(v.x, v.y);
    }
}

// fill CSR: src only, no atomics, no dinv reads
__global__ void k_csr_fill() {
    int e = blockIdx.x * blockDim.x + threadIdx.x;
    if (e >= NE) return;
    int2 sd = g_sd[e];
    int d = sd.y & 0x1FFFF;
    int rank = ((unsigned)sd.y) >> 17;
    g_csrc[g_off[d] + rank] = sd.x;
}

// ---------------- fused layer 1: gather-sum(x~,64)·dinv + HMMA W1 + relu -> H~1(fp16) ----------------
#define LDA1 72    // halves (row = 144B)
__global__ __launch_bounds__(256)
void k_fused1(const float* __restrict__ bias) {
    __shared__ __half As[64 * LDA1];     // 9.2 KB
    __shared__ __half Wh[64 * 136];      // 17.4 KB

    const int tid = threadIdx.x;
    const int lane = tid & 31;
    const int w = tid >> 5;
    const int node_base = blockIdx.x * 64;
    const unsigned* __restrict__ Xu = (const unsigned*)g_xh;
    const int* __restrict__ C = g_csrc;
    unsigned* As_u = (unsigned*)As;

#pragma unroll
    for (int it = 0; it < 4; ++it) {
        int idx = tid + it * 256;
        int row = idx >> 4, ch = idx & 15;
        uint4 v = ((const uint4*)g_w1h)[idx];
        *(uint4*)&Wh[row * 136 + ch * 8] = v;
    }

    // phase 1: warp-per-node gather SUM (features pre-scaled), final ×dinv[node]
    for (int j = w; j < 64; j += 8) {
        int node = node_base + j;
        float2 acc;
        if (node < NN) {
            acc = h2f(Xu[node * 32 + lane]);   // self term x~[i]
            int beg = g_off[node];
            int cnt = g_degi[node];
            int k = 0;
            for (; k + 4 <= cnt; k += 4) {
                int s0 = C[beg + k];
                int s1 = C[beg + k + 1];
                int s2 = C[beg + k + 2];
                int s3 = C[beg + k + 3];
                float2 v0 = h2f(Xu[s0 * 32 + lane]);
                float2 v1 = h2f(Xu[s1 * 32 + lane]);
                float2 v2 = h2f(Xu[s2 * 32 + lane]);
                float2 v3 = h2f(Xu[s3 * 32 + lane]);
                acc.x += (v0.x + v1.x) + (v2.x + v3.x);
                acc.y += (v0.y + v1.y) + (v2.y + v3.y);
            }
            for (; k < cnt; ++k) {
                float2 v0 = h2f(Xu[C[beg + k] * 32 + lane]);
                acc.x += v0.x;
                acc.y += v0.y;
            }
            float di = g_dinv[node];
            acc.x *= di; acc.y *= di;
        } else {
            acc.x = 0.0f; acc.y = 0.0f;
        }
        __half2 h = __floats2half2_rn(acc.x, acc.y);
        As_u[j * (LDA1 / 2) + lane] = *(unsigned*)&h;
    }
    __syncthreads();

    // phase 2: HMMA GEMM (64x64) x (64x128)
    const int mt = w >> 1;
    const int nh = w & 1;
    float acc[8][4];
#pragma unroll
    for (int i = 0; i < 8; ++i)
#pragma unroll
        for (int jj = 0; jj < 4; ++jj) acc[i][jj] = 0.0f;

    mma_gemm_phase<C_IN, LDA1>(s2u(As), s2u(Wh), lane, mt, nh, acc);

    // epilogue: bias + relu, pre-scale by dinv[row] -> fp16 store (H~1)
    const int gid = lane >> 2, tig = lane & 3;
    const int r0 = node_base + mt * 16 + gid;
    const int r1 = r0 + 8;
    const float d0 = (r0 < NN) ? g_dinv[r0] : 0.0f;
    const float d1 = (r1 < NN) ? g_dinv[r1] : 0.0f;
#pragma unroll
    for (int nt = 0; nt < 8; ++nt) {
        int col = nh * 64 + nt * 8 + tig * 2;
        float b0v = __ldg(&bias[col]);
        float b1v = __ldg(&bias[col + 1]);
        if (r0 < NN) {
            __half2 h = __floats2half2_rn(fmaxf(acc[nt][0] + b0v, 0.0f) * d0,
                                          fmaxf(acc[nt][1] + b1v, 0.0f) * d0);
            ((unsigned*)g_h1h)[(size_t)r0 * 64 + (col >> 1)] = *(unsigned*)&h;
        }
        if (r1 < NN) {
            __half2 h = __floats2half2_rn(fmaxf(acc[nt][2] + b0v, 0.0f) * d1,
                                          fmaxf(acc[nt][3] + b1v, 0.0f) * d1);
            ((unsigned*)g_h1h)[(size_t)r1 * 64 + (col >> 1)] = *(unsigned*)&h;
        }
    }
}

// ---------------- fused layer 2: gather-sum(H~1,128)·dinv + HMMA W2(tiled 32) + relu + mean-pool ----------------
#define LDA2 136                      // halves (row = 272B)
#define F2_AS_B   (64 * LDA2 * 2)     // 17408
#define F2_WS_B   (32 * 136 * 2)      // 8704 (tiled W)
#define F2_OUT_B  (64 * 128 * 4)      // 32768 (overlays As+Ws after GEMM)
#define F2_SMEM   (F2_OUT_B + 256)    // 33024

__global__ __launch_bounds__(256)
void k_fused2(const float* __restrict__ bias, const void* __restrict__ batch) {
    extern __shared__ char smb[];
    __half* As = (__half*)smb;                       // [64][136]
    __half* Ws = (__half*)(smb + F2_AS_B);           // [32][136] (tile)
    float*  out = (float*)smb;                       // [64][128], reused after GEMM
    int*    sbat = (int*)(smb + F2_OUT_B);           // [64]

    const int tid = threadIdx.x;
    const int lane = tid & 31;
    const int w = tid >> 5;
    const int node_base = blockIdx.x * 64;
    const int lim = min(64, NN - node_base);
    const uint2* __restrict__ Hu = (const uint2*)g_h1h;
    const int* __restrict__ C = g_csrc;
    uint2* As_u2 = (uint2*)As;

    if (tid < 64) {
        int n = node_base + tid;
        int g = 0;
        if (n < NN) g = read_idx(batch, n);
        sbat[tid] = min(max(g, 0), NG - 1);
    }

    // phase 1: warp-per-node gather SUM (pre-scaled), final ×dinv[node]
    for (int j = w; j < 64; j += 8) {
        int node = node_base + j;
        float4 acc;
        if (node < NN) {
            uint2 su = Hu[(size_t)node * 32 + lane];
            float2 sa = h2f(su.x), sb = h2f(su.y);
            acc = make_float4(sa.x, sa.y, sb.x, sb.y);
            int beg = g_off[node];
            int cnt = g_degi[node];
            int k = 0;
            for (; k + 4 <= cnt; k += 4) {
                int s0 = C[beg + k];
                int s1 = C[beg + k + 1];
                int s2 = C[beg + k + 2];
                int s3 = C[beg + k + 3];
                uint2 u0 = Hu[(size_t)s0 * 32 + lane];
                uint2 u1 = Hu[(size_t)s1 * 32 + lane];
                uint2 u2 = Hu[(size_t)s2 * 32 + lane];
                uint2 u3 = Hu[(size_t)s3 * 32 + lane];
                float2 a0 = h2f(u0.x), b0 = h2f(u0.y);
                float2 a1 = h2f(u1.x), b1 = h2f(u1.y);
                float2 a2 = h2f(u2.x), b2 = h2f(u2.y);
                float2 a3 = h2f(u3.x), b3 = h2f(u3.y);
                acc.x += (a0.x + a1.x) + (a2.x + a3.x);
                acc.y += (a0.y + a1.y) + (a2.y + a3.y);
                acc.z += (b0.x + b1.x) + (b2.x + b3.x);
                acc.w += (b0.y + b1.y) + (b2.y + b3.y);
            }
            for (; k < cnt; ++k) {
                uint2 u0 = Hu[(size_t)C[beg + k] * 32 + lane];
                float2 a0 = h2f(u0.x), b0 = h2f(u0.y);
                acc.x += a0.x;
                acc.y += a0.y;
                acc.z += b0.x;
                acc.w += b0.y;
            }
            float di = g_dinv[node];
            acc.x *= di; acc.y *= di; acc.z *= di; acc.w *= di;
        } else {
            acc = make_float4(0.0f, 0.0f, 0.0f, 0.0f);
        }
        __half2 h0 = __floats2half2_rn(acc.x, acc.y);
        __half2 h1 = __floats2half2_rn(acc.z, acc.w);
        uint2 u;
        u.x = *(unsigned*)&h0;
        u.y = *(unsigned*)&h1;
        As_u2[j * (LDA2 / 4) + lane] = u;
    }
    __syncthreads();

    // phase 2: HMMA GEMM (64x128) x (128x128), W tiled 32 rows/iter
    const int mt = w >> 1;
    const int nh = w & 1;
    float acc[8][4];
#pragma unroll
    for (int i = 0; i < 8; ++i)
#pragma unroll
        for (int jj = 0; jj < 4; ++jj) acc[i][jj] = 0.0f;

    const unsigned asb = s2u(As);
    const unsigned wsb = s2u(Ws);
    const unsigned a_base = asb + (((mt * 16 + (lane & 15)) * LDA2) + ((lane >> 4) << 3)) * 2;
    const int brow = (lane & 7) + (lane & 8);
    const int bcol = nh * 64 + ((lane & 16) >> 1);

#pragma unroll
    for (int k0 = 0; k0 < C_HID; k0 += 32) {
        // stage W rows [k0, k0+32) into Ws
#pragma unroll
        for (int it = 0; it < 2; ++it) {
            int idx = tid + it * 256;          // 512 uint4 chunks (32 rows x 16)
            int row = idx >> 4, ch = idx & 15;
            uint4 v = ((const uint4*)g_w2h)[(k0 + row) * 16 + ch];
            *(uint4*)&Ws[row * 136 + ch * 8] = v;
        }
        __syncthreads();
#pragma unroll
        for (int kk = 0; kk < 32; kk += 16) {
            unsigned a0, a1, a2, a3;
            ldsm_x4(a0, a1, a2, a3, a_base + (k0 + kk) * 2);
#pragma unroll
            for (int p = 0; p < 4; ++p) {
                unsigned b0, b1, b2, b3;
                unsigned baddr = wsb + (((kk + brow) * 136) + bcol + p * 16) * 2;
                ldsm_x4_t(b0, b1, b2, b3, baddr);
                mma_f16(acc[2 * p],     a0, a1, a2, a3, b0, b1);
                mma_f16(acc[2 * p + 1], a0, a1, a2, a3, b2, b3);
            }
        }
        __syncthreads();
    }

    // phase 3: bias + relu into smem out[64][128] (overlay of As+Ws)
    const int gid = lane >> 2, tig = lane & 3;
    const int r0l = mt * 16 + gid, r1l = r0l + 8;
#pragma unroll
    for (int nt = 0; nt < 8; ++nt) {
        int col = nh * 64 + nt * 8 + tig * 2;
        float b0v = __ldg(&bias[col]);
        float b1v = __ldg(&bias[col + 1]);
        out[r0l * 128 + col]     = fmaxf(acc[nt][0] + b0v, 0.0f);
        out[r0l * 128 + col + 1] = fmaxf(acc[nt][1] + b1v, 0.0f);
        out[r1l * 128 + col]     = fmaxf(acc[nt][2] + b0v, 0.0f);
        out[r1l * 128 + col + 1] = fmaxf(acc[nt][3] + b1v, 0.0f);
    }
    __syncthreads();

    // phase 4: per-column pooled reduction over sorted batch ids
    if (tid < 128 && lim > 0) {
        int c = tid;
        float accp = 0.0f;
        int g = sbat[0];
        for (int r = 0; r < lim; ++r) {
            int gb = sbat[r];
            if (gb != g) {
                atomicAdd(&g_pooled[g * C_HID + c], accp);
                g = gb; accp = 0.0f;
            }
            accp += out[r * 128 + c];
        }
        atomicAdd(&g_pooled[g * C_HID + c], accp);
    }
}

// ---------------- classifier head: one block per graph, warp-reduced dots ----------------
__global__ __launch_bounds__(32) void k_final(const float* __restrict__ Wc,
                                              const float* __restrict__ bc,
                                              float* __restrict__ out) {
    int g = blockIdx.x;
    int lane = threadIdx.x;
    float inv = 1.0f / fmaxf(g_cnt[g], 1.0f);
    float p[4];
#pragma unroll
    for (int i = 0; i < 4; ++i) p[i] = g_pooled[g * C_HID + i * 32 + lane];
#pragma unroll
    for (int c = 0; c < NC; ++c) {
        float s = 0.0f;
#pragma unroll
        for (int i = 0; i < 4; ++i)
            s += p[i] * __ldg(&Wc[(i * 32 + lane) * NC + c]);
#pragma unroll
        for (int o = 16; o > 0; o >>= 1)
            s += __shfl_down_sync(0xFFFFFFFFu, s, o);
        if (lane == 0) out[g * NC + c] = s * inv + bc[c];
    }
}

// ---------------- launch ----------------
extern "C" void kernel_launch(void* const* d_in, const int* in_sizes, int n_in,
                              void* d_out, int out_size) {
    const float* x = 0; const float* W1 = 0; const float* b1 = 0;
    const float* W2 = 0; const float* b2 = 0; const float* Wc = 0;
    const float* bc = 0; const void* ei = 0; const void* batch = 0;
    for (int i = 0; i < n_in; ++i) {
        int s = in_sizes[i];
        void* p = d_in[i];
        if      (s == NN * C_IN)     x  = (const float*)p;
        else if (s == C_IN * C_HID)  W1 = (const float*)p;
        else if (s == C_HID * C_HID) W2 = (const float*)p;
        else if (s == C_HID * NC)    Wc = (const float*)p;
        else if (s == NC)            bc = (const float*)p;
        else if (s == 2 * NE)        ei = p;
        else if (s == NN)            batch = p;
        else if (s == C_HID)         { if (!b1) b1 = (const float*)p; else b2 = (const float*)p; }
    }
    if (!b2) b2 = b1;
    float* out = (float*)d_out;
    (void)out_size;

    static int attr_done = 0;
    if (!attr_done) {
        cudaFuncSetAttribute(k_fused2, cudaFuncAttributeMaxDynamicSharedMemorySize, F2_SMEM);
        attr_done = 1;
    }

    const int T = 256;
    const int CVT_BLKS = (NT_X + NT_W1 + NT_W2 + T - 1) / T;

    k_init<<<NBLK, T>>>(ei);                              // 0 (zero + dtype detect)
    k_edge_prep<<<(NE + T - 1) / T, T>>>(ei);             // 1
    k_blocksum<<<NBLK, T>>>(batch);                       // 2 (scan sums + batch histogram)
    k_offsets<<<NBLK, T>>>();                             // 3 (offsets + dinv)
    k_convert<<<CVT_BLKS, T>>>(x, W1, W2);                // 4 (x pre-scaled by dinv)
    k_csr_fill<<<(NE + T - 1) / T, T>>>();                // 5 (src-only payload)

    k_fused1<<<NTILE, T>>>(b1);                           // 6
    k_fused2<<<NTILE, T, F2_SMEM>>>(b2, batch);           // 7
    k_final<<<NG, 32>>>(Wc, bc, out);                     // 8
}